// round 15
// baseline (speedup 1.0000x reference)
#include <cuda_runtime.h>
#include <cstdint>

#define B_    4
#define T_    1024
#define DIM_  512
#define POOL_ 64
#define K_    50
#define TK_   2      // tokens per k1 block (packed in f32x2)

// Scratch (device globals: allocation-free per harness rules)
__device__ __align__(16) float g_y[B_ * POOL_ * POOL_];   // y[b][t<64][p]
__device__ int   g_idx[T_ * K_];                          // top-50 indices per t
__device__ __align__(16) float g_z[B_ * POOL_ * DIM_];    // z[b][j][d]

// packed fp32x2 ops (Blackwell FFMA2 — only reachable via PTX)
#define FMA2(d, a, b) \
    asm("fma.rn.f32x2 %0, %1, %2, %3;" : "=l"(d) : "l"(a), "l"(b), "l"(d))
#define ADD2(d, a, b) \
    asm("add.rn.f32x2 %0, %1, %2;" : "=l"(d) : "l"(a), "l"(b))
#define UNPACK2(lo, hi, v) \
    asm("mov.b64 {%0, %1}, %2;" : "=f"(lo), "=f"(hi) : "l"(v))

// One K-step with ALL addresses as base-register + compile-time immediate:
// zero per-iteration address arithmetic (ptxas folds literals into the
// load's offset field; computed-register operands would defeat that).
#define K1_STEP(D2) do {                                                     \
    unsigned long long w0x, w0y, w1x, w1y;                                   \
    asm("ld.global.nc.v2.u64 {%0,%1}, [%2+%3];"                              \
        : "=l"(w0x), "=l"(w0y) : "l"(wbase), "n"((D2) * 512));               \
    asm("ld.global.nc.v2.u64 {%0,%1}, [%2+%3];"                              \
        : "=l"(w1x), "=l"(w1y) : "l"(wbase), "n"((D2) * 512 + 256));         \
    _Pragma("unroll")                                                        \
    for (int bt = 0; bt < 8; bt++) {                                         \
        unsigned long long xv0, xv1;                                         \
        asm("ld.shared.v2.b64 {%0,%1}, [%2+%3];"                             \
            : "=l"(xv0), "=l"(xv1) : "r"(xb[bt]), "n"((D2) * 16));           \
        FMA2(acc[bt][0], xv0, w0x);                                          \
        FMA2(acc[bt][1], xv0, w0y);                                          \
        FMA2(acc[bt][0], xv1, w1x);                                          \
        FMA2(acc[bt][1], xv1, w1y);                                          \
    }                                                                        \
} while (0)

// ---------------------------------------------------------------------------
// Kernel 1 (round-5 structure): 2 tokens/block, grid=512, block=256.
// f32x2 lanes = POOL PAIRS; x staged lane-duplicated in smem.
// Thread (dc=tid>>4, pg=tid&15): pools pg*4..pg*4+3, 8 (b,tok) rows,
// dims [dc*32, dc*32+32). Butterfly + smem reduce, LN + stable top-50 tail.
// NEW: immediate-offset loads (K1_STEP) — no per-access address math.
// ---------------------------------------------------------------------------
__global__ __launch_bounds__(256) void k1_reduce_topk(
        const float* __restrict__ x,
        const float* __restrict__ w1,
        const float* __restrict__ b1,
        const float* __restrict__ g1,
        const float* __restrict__ bt1) {
    __shared__ __align__(16) float2 pool2[B_ * TK_ * DIM_];  // 32KB
    __shared__ float sv[TK_ * POOL_];
    __shared__ float wsum[4][B_], wsq[4][B_];
    float* poolf = reinterpret_cast<float*>(pool2);

    const int t0  = blockIdx.x * TK_;
    const int tid = threadIdx.x;
    const int pg  = tid & 15;
    const int dc  = tid >> 4;

    uint32_t sx;
    asm("{ .reg .u64 t; cvta.to.shared.u64 t, %1; cvt.u32.u64 %0, t; }"
        : "=r"(sx) : "l"(pool2));

    // ---- phase 1: load x rows, lane-duplicated ----
    #pragma unroll
    for (int i = tid; i < B_ * (DIM_ / 4); i += 256) {
        int b = i >> 7, j = i & 127;
        const float* xb_ = x + ((size_t)b * T_ + t0) * DIM_;
        float4 v0 = reinterpret_cast<const float4*>(xb_)[j];
        float4 v1 = reinterpret_cast<const float4*>(xb_ + DIM_)[j];
        float2* d0 = pool2 + (b * 2 + 0) * DIM_ + j * 4;
        d0[0] = make_float2(v0.x, v0.x);
        d0[1] = make_float2(v0.y, v0.y);
        d0[2] = make_float2(v0.z, v0.z);
        d0[3] = make_float2(v0.w, v0.w);
        float2* d1 = pool2 + (b * 2 + 1) * DIM_ + j * 4;
        d1[0] = make_float2(v1.x, v1.x);
        d1[1] = make_float2(v1.y, v1.y);
        d1[2] = make_float2(v1.z, v1.z);
        d1[3] = make_float2(v1.w, v1.w);
    }
    __syncthreads();

    // ---- main loop: base registers + immediate offsets only ----
    unsigned long long acc[8][2] = {};
    // w1 base for this thread: dim block dc*32 (8192B per dc), pool chunk pg
    const unsigned long long wbase =
        (unsigned long long)w1 + (size_t)dc * 8192 + (size_t)pg * 16;
    // smem base per (b,tok) row: sx + bt*4096 + dc*256
    uint32_t xb[8];
    #pragma unroll
    for (int bt = 0; bt < 8; bt++)
        xb[bt] = sx + (uint32_t)(bt * 4096 + dc * 256);

    K1_STEP(0);  K1_STEP(1);  K1_STEP(2);  K1_STEP(3);
    K1_STEP(4);  K1_STEP(5);  K1_STEP(6);  K1_STEP(7);
    K1_STEP(8);  K1_STEP(9);  K1_STEP(10); K1_STEP(11);
    K1_STEP(12); K1_STEP(13); K1_STEP(14); K1_STEP(15);

    // ---- reduce over dc: butterfly (dc pairs), then smem ----
    #pragma unroll
    for (int bt = 0; bt < 8; bt++) {
        #pragma unroll
        for (int pr = 0; pr < 2; pr++) {
            unsigned long long o = __shfl_xor_sync(0xffffffffu, acc[bt][pr], 16);
            ADD2(acc[bt][pr], acc[bt][pr], o);
        }
    }
    __syncthreads();   // all x reads done; reuse poolf for partials

    if ((tid & 16) == 0) {
        const int w = tid >> 5;
        #pragma unroll
        for (int bt = 0; bt < 8; bt++) {
            #pragma unroll
            for (int pr = 0; pr < 2; pr++) {
                float lo, hi;
                UNPACK2(lo, hi, acc[bt][pr]);
                poolf[w * 512 + bt * 64 + pg * 4 + pr * 2 + 0] = lo;
                poolf[w * 512 + bt * 64 + pg * 4 + pr * 2 + 1] = hi;
            }
        }
    }
    __syncthreads();

    // ---- tail on first 128 threads: tk = tid>>6, pp = tid&63 ----
    float vv[B_];
    if (tid < TK_ * POOL_) {
        const int tk = tid >> 6;
        const int pp = tid & 63;
        const float bias = b1[pp];
        #pragma unroll
        for (int b = 0; b < B_; b++) {
            float a = bias;
            #pragma unroll
            for (int w = 0; w < 8; w++)
                a += poolf[w * 512 + (b * TK_ + tk) * 64 + pp];
            vv[b] = fmaxf(a, 0.f);
        }
        float s[B_], q[B_];
        #pragma unroll
        for (int b = 0; b < B_; b++) { s[b] = vv[b]; q[b] = vv[b] * vv[b]; }
        #pragma unroll
        for (int off = 16; off > 0; off >>= 1) {
            #pragma unroll
            for (int b = 0; b < B_; b++) {
                s[b] += __shfl_xor_sync(0xffffffffu, s[b], off);
                q[b] += __shfl_xor_sync(0xffffffffu, q[b], off);
            }
        }
        const int w = tid >> 5;
        if ((tid & 31) == 0) {
            #pragma unroll
            for (int b = 0; b < B_; b++) { wsum[w][b] = s[b]; wsq[w][b] = q[b]; }
        }
    }
    __syncthreads();

    if (tid < TK_ * POOL_) {
        const int tk = tid >> 6;
        const int pp = tid & 63;
        const int t  = t0 + tk;
        const float gp = g1[pp], bp = bt1[pp];

        float ysum = 0.f;
        float yv[B_];
        #pragma unroll
        for (int b = 0; b < B_; b++) {
            float S = wsum[tk * 2][b] + wsum[tk * 2 + 1][b];
            float Q = wsq[tk * 2][b]  + wsq[tk * 2 + 1][b];
            float m   = S * (1.f / POOL_);
            float var = Q * (1.f / POOL_) - m * m;
            float r   = rsqrtf(var + 1e-5f);
            yv[b] = (vv[b] - m) * r * gp + bp;
            ysum += yv[b];
        }

        if (t < POOL_) {
            #pragma unroll
            for (int b = 0; b < B_; b++)
                g_y[(b * POOL_ + t) * POOL_ + pp] = yv[b];
        }

        sv[tk * POOL_ + pp] = ysum;
        __syncwarp();
        asm volatile("bar.sync 1, 128;" ::: "memory");

        const float mine = ysum;
        int rank = 0;
        #pragma unroll
        for (int j = 0; j < POOL_; j++) {
            float o = sv[tk * POOL_ + j];
            rank += (o > mine) || ((o == mine) && (j < pp));
        }
        if (rank < K_) g_idx[t * K_ + rank] = pp;
    }
}

// ---------------------------------------------------------------------------
// Kernel 2: z[b,j,:] = LN(relu(y[b,j,:] @ w2 + b2))   (256 distinct rows)
// grid = B_*POOL_, block = 512
// ---------------------------------------------------------------------------
__global__ void k2_expand(const float* __restrict__ w2,
                          const float* __restrict__ b2,
                          const float* __restrict__ g2,
                          const float* __restrict__ bt2) {
    const int bj = blockIdx.x;
    const int d  = threadIdx.x;

    __shared__ float yr[POOL_];
    if (d < POOL_) yr[d] = g_y[bj * POOL_ + d];
    __syncthreads();

    float acc = b2[d];
    #pragma unroll
    for (int p = 0; p < POOL_; p++)
        acc += yr[p] * w2[p * DIM_ + d];

    float v = fmaxf(acc, 0.f);

    float s = v, q = v * v;
    #pragma unroll
    for (int off = 16; off > 0; off >>= 1) {
        s += __shfl_xor_sync(0xffffffffu, s, off);
        q += __shfl_xor_sync(0xffffffffu, q, off);
    }
    __shared__ float ps[16], pq[16];
    const int w = d >> 5;
    if ((d & 31) == 0) { ps[w] = s; pq[w] = q; }
    __syncthreads();
    float S = 0.f, Q = 0.f;
    #pragma unroll
    for (int i = 0; i < 16; i++) { S += ps[i]; Q += pq[i]; }

    float m   = S * (1.f / DIM_);
    float var = Q * (1.f / DIM_) - m * m;
    g_z[bj * DIM_ + d] = (v - m) * rsqrtf(var + 1e-5f) * g2[d] + bt2[d];
}

// ---------------------------------------------------------------------------
// Kernel 3: out[b,t,k,:] = z[b, idx[t,k], :]  — the 419 MB write stream.
// Round-5 configuration (__ldg reads, __stcs streaming stores). At the
// HBM-write roofline.
// ---------------------------------------------------------------------------
__global__ void k3_gather(float* __restrict__ out) {
    const int warp = threadIdx.x >> 5;
    const int lane = threadIdx.x & 31;
    const unsigned base = blockIdx.x * 64u;

    #pragma unroll
    for (int i = 0; i < 4; i++) {
        unsigned r   = base + warp + i * 16;
        unsigned b   = r / (unsigned)(T_ * K_);
        unsigned rem = r - b * (unsigned)(T_ * K_);
        unsigned t   = rem / K_;
        unsigned k   = rem - t * K_;
        int j = g_idx[t * K_ + k];

        const float4* src = reinterpret_cast<const float4*>(g_z)
                            + (size_t)(b * POOL_ + j) * (DIM_ / 4);
        float4* dst = reinterpret_cast<float4*>(out)
                      + (size_t)r * (DIM_ / 4);
        #pragma unroll
        for (int cc = 0; cc < 4; cc++) {
            float4 v = __ldg(src + lane + 32 * cc);
            __stcs(dst + lane + 32 * cc, v);
        }
    }
}

// ---------------------------------------------------------------------------
extern "C" void kernel_launch(void* const* d_in, const int* in_sizes, int n_in,
                              void* d_out, int out_size) {
    const float* x   = (const float*)d_in[0];
    const float* w1  = (const float*)d_in[1];
    const float* b1  = (const float*)d_in[2];
    const float* g1  = (const float*)d_in[3];
    const float* bt1 = (const float*)d_in[4];
    const float* w2  = (const float*)d_in[5];
    const float* b2  = (const float*)d_in[6];
    const float* g2  = (const float*)d_in[7];
    const float* bt2 = (const float*)d_in[8];
    float* out = (float*)d_out;

    k1_reduce_topk<<<T_ / TK_, 256>>>(x, w1, b1, g1, bt1);
    k2_expand<<<B_ * POOL_, DIM_>>>(w2, b2, g2, bt2);
    k3_gather<<<(B_ * T_ * K_) / 64, 512>>>(out);
}